// round 1
// baseline (speedup 1.0000x reference)
#include <cuda_runtime.h>
#include <cstdint>

#define T_STEPS 50
#define FEAT    14
#define MDIM    3
#define DEC     128
#define DT_     0.1f
#define ALPHA_  0.3f
#define DUMMY_DX_ 50.0f
#define ROWS    32
#define THREADS 128

// ---------------- packed f32x2 helpers (sm_103a) ----------------
__device__ __forceinline__ void ffma2(unsigned long long &acc,
                                      unsigned long long a,
                                      unsigned long long b) {
    asm("fma.rn.f32x2 %0, %1, %2, %0;" : "+l"(acc) : "l"(a), "l"(b));
}
__device__ __forceinline__ unsigned long long pk(float lo, float hi) {
    unsigned long long r;
    asm("mov.b64 %0, {%1, %2};" : "=l"(r) : "f"(lo), "f"(hi));
    return r;
}
__device__ __forceinline__ float2 upk(unsigned long long v) {
    float2 f;
    asm("mov.b64 {%0, %1}, %2;" : "=f"(f.x), "=f"(f.y) : "l"(v));
    return f;
}

struct __align__(16) SmemLayout {
    union {
        float inbuf[ROWS][256];   // phase-1 staging of [proj, enc]
        float W2T[128][132];      // W2T[j][k] = W2[k][j], pad 132 -> LDS.128 conflict-free
    } u;
    float h1s[ROWS][128];         // h1 per row (k-contiguous for float4 broadcast reads)
    float red[128][33];           // per-(j,r) contributions for W3 reduction
    float W1v[11][128];           // W1 rows 256..266 (env + merger part)
    float envmc[ROWS][12];        // normalized env(8) + mc(3)
    float partial[4][ROWS];
    float ems[8];
    float eiss[8];
};

__global__ void __launch_bounds__(THREADS, 2)
forward_sim_kernel(const float* __restrict__ proj,
                   const float* __restrict__ enc,
                   const float* __restrict__ idm,
                   const float* __restrict__ mc,
                   const float* __restrict__ env_mean,
                   const float* __restrict__ env_var,
                   const float* __restrict__ W1,
                   const float* __restrict__ b1,
                   const float* __restrict__ W2,
                   const float* __restrict__ b2,
                   const float* __restrict__ W3,
                   const float* __restrict__ b3,
                   float* __restrict__ out,
                   int B) {
    extern __shared__ char smem_raw[];
    SmemLayout* s = reinterpret_cast<SmemLayout*>(smem_raw);

    const int tid = threadIdx.x;
    const int j   = tid;                 // hidden column owned by this thread
    const int row0 = blockIdx.x * ROWS;

    float* out_disp = out;                             // (B, 51)
    float* out_act  = out + (size_t)B * (T_STEPS + 1); // (B, 50)

    // ---------------- constants to smem ----------------
    if (tid < 8) {
        s->ems[tid]  = env_mean[tid];
        s->eiss[tid] = 1.0f / sqrtf(env_var[tid]);
    }
    // W1 varying part (rows 256..266)
    for (int i = tid; i < 11 * 128; i += THREADS) {
        int rr = i >> 7, cc = i & 127;
        s->W1v[rr][cc] = W1[(256 + rr) * 128 + cc];
    }
    // stage [proj, enc] for this tile
    for (int i = tid; i < ROWS * 128; i += THREADS) {
        int r = i >> 7, c = i & 127;
        int row = row0 + r;
        bool ok = row < B;
        s->u.inbuf[r][c]       = ok ? proj[(size_t)row * 128 + c] : 0.0f;
        s->u.inbuf[r][128 + c] = ok ? enc [(size_t)row * 128 + c] : 0.0f;
    }
    __syncthreads();

    // ---------------- phase 1: base = [proj,enc] @ W1[:256] + b1 ----------------
    const float b1j = b1[j];
    float base[ROWS];
#pragma unroll
    for (int r = 0; r < ROWS; r++) base[r] = b1j;

    for (int k = 0; k < 256; k += 4) {
        float w0 = W1[(k + 0) * 128 + j];
        float w1 = W1[(k + 1) * 128 + j];
        float w2 = W1[(k + 2) * 128 + j];
        float w3 = W1[(k + 3) * 128 + j];
#pragma unroll
        for (int r = 0; r < ROWS; r++) {
            float4 x = *(const float4*)&s->u.inbuf[r][k];
            float v = base[r];
            v = fmaf(x.x, w0, v);
            v = fmaf(x.y, w1, v);
            v = fmaf(x.z, w2, v);
            v = fmaf(x.w, w3, v);
            base[r] = v;
        }
    }
    __syncthreads();

    // ---------------- load W2 transposed into smem (overwrites inbuf) ----------------
    for (int i = tid; i < 128 * 128; i += THREADS) {
        int k = i >> 7, c = i & 127;     // coalesced read of W2[k][c]
        s->u.W2T[c][k] = W2[i];
    }

    const float w3j = W3[j];
    const float b2j = b2[j];
    const float b3v = b3[0];

    // hoist W1v column j into registers (reused every step)
    float w1vj[11];
#pragma unroll
    for (int i = 0; i < 11; i++) w1vj[i] = s->W1v[i][j];

    // ---------------- per-row state (threads 0..31) ----------------
    float ego_v = 0.f, ego_a = 0.f, ego_x = 0.f, disp = 0.f;
    int  myrow = row0 + tid;
    bool rowok = (tid < ROWS) && (myrow < B);
    if (rowok) {
        const float* p0 = idm + (size_t)myrow * T_STEPS * FEAT;
        ego_v = p0[0];
        ego_a = p0[11];
        ego_x = p0[3];
        out_disp[(size_t)myrow * (T_STEPS + 1)] = 0.0f;   // disp0
    }
    __syncthreads();

    // ---------------- main time loop ----------------
    for (int t = 0; t < T_STEPS; t++) {
        // phase A: env features (threads 0..31)
        if (rowok) {
            const float* it = idm + ((size_t)myrow * T_STEPS + t) * FEAT;
            float fv = it[1], mv = it[2], fx = it[4], mx = it[5];
            float fa = it[12], me = it[13];
            float ef_dx = fx - ego_x;
            float em_dx = (mx - ego_x) * me + (1.0f - me) * DUMMY_DX_;
            float ef_dv = ego_v - fv;
            float em_dv = (ego_v - mv) * me;   // dummy_dv = 0
            float e0 = ego_v, e1 = fv, e2 = ego_a, e3 = fa;
            float e4 = ef_dv, e5 = ef_dx, e6 = em_dv, e7 = em_dx;
            s->envmc[tid][0] = (e0 - s->ems[0]) * s->eiss[0];
            s->envmc[tid][1] = (e1 - s->ems[1]) * s->eiss[1];
            s->envmc[tid][2] = (e2 - s->ems[2]) * s->eiss[2];
            s->envmc[tid][3] = (e3 - s->ems[3]) * s->eiss[3];
            s->envmc[tid][4] = (e4 - s->ems[4]) * s->eiss[4];
            s->envmc[tid][5] = (e5 - s->ems[5]) * s->eiss[5];
            s->envmc[tid][6] = (e6 - s->ems[6]) * s->eiss[6];
            s->envmc[tid][7] = (e7 - s->ems[7]) * s->eiss[7];
            const float* mt = mc + ((size_t)myrow * T_STEPS + t) * MDIM;
            s->envmc[tid][8]  = mt[0];
            s->envmc[tid][9]  = mt[1];
            s->envmc[tid][10] = mt[2];
        }
        __syncthreads();

        // phase B: h1[r][j] = leaky(base + envmc @ W1v)
#pragma unroll
        for (int r = 0; r < ROWS; r++) {
            float v = base[r];
#pragma unroll
            for (int i = 0; i < 11; i++) v = fmaf(s->envmc[r][i], w1vj[i], v);
            v = (v >= 0.0f) ? v : ALPHA_ * v;
            s->h1s[r][j] = v;
        }
        __syncthreads();

        // phase C: h2pre[r][j] = sum_k W2[k][j] * h1[r][k]  (f32x2 packed FMA)
        unsigned long long acc[ROWS];
#pragma unroll
        for (int r = 0; r < ROWS; r++) acc[r] = 0ull;

        const float4* wrow = (const float4*)&s->u.W2T[j][0];
#pragma unroll 2
        for (int k4 = 0; k4 < 32; k4++) {
            float4 w = wrow[k4];
            unsigned long long w01 = pk(w.x, w.y);
            unsigned long long w23 = pk(w.z, w.w);
#pragma unroll
            for (int r = 0; r < ROWS; r++) {
                float4 h = *(const float4*)&s->h1s[r][k4 * 4];
                ffma2(acc[r], w01, pk(h.x, h.y));
                ffma2(acc[r], w23, pk(h.z, h.w));
            }
        }

        // phase D: h2 = leaky(.), contribution to output scalar
#pragma unroll
        for (int r = 0; r < ROWS; r++) {
            float2 p = upk(acc[r]);
            float h2v = p.x + p.y + b2j;
            h2v = (h2v >= 0.0f) ? h2v : ALPHA_ * h2v;
            s->red[j][r] = h2v * w3j;
        }
        __syncthreads();

        // phase E: partial reductions over j (4 groups of 32)
        {
            int rr = tid & 31, q = tid >> 5;
            float ssum = 0.0f;
#pragma unroll
            for (int jj = 0; jj < 32; jj++) ssum += s->red[q * 32 + jj][rr];
            s->partial[q][rr] = ssum;
        }
        __syncthreads();

        // phase F: finalize a, update state, write outputs (threads 0..31)
        if (rowok) {
            float a = s->partial[0][tid] + s->partial[1][tid] +
                      s->partial[2][tid] + s->partial[3][tid] + b3v;
            float move = ego_v * DT_ + 0.5f * a * DT_ * DT_;
            disp  += move;
            ego_x += move;
            ego_v += a * DT_;
            ego_a  = a;
            out_act [(size_t)myrow * T_STEPS + t]          = a;
            out_disp[(size_t)myrow * (T_STEPS + 1) + t + 1] = disp;
        }
        // no sync needed here: envmc rewrite is fenced by the sync after phase A
    }
}

extern "C" void kernel_launch(void* const* d_in, const int* in_sizes, int n_in,
                              void* d_out, int out_size) {
    const float* proj     = (const float*)d_in[0];
    const float* enc      = (const float*)d_in[1];
    const float* idm      = (const float*)d_in[2];
    const float* mc       = (const float*)d_in[3];
    const float* env_mean = (const float*)d_in[4];
    const float* env_var  = (const float*)d_in[5];
    const float* W1       = (const float*)d_in[6];
    const float* b1       = (const float*)d_in[7];
    const float* W2       = (const float*)d_in[8];
    const float* b2       = (const float*)d_in[9];
    const float* W3       = (const float*)d_in[10];
    const float* b3       = (const float*)d_in[11];
    float* out = (float*)d_out;

    int B = in_sizes[0] / 128;   // proj_latent is (B, 128)

    int smem = (int)sizeof(SmemLayout);
    cudaFuncSetAttribute(forward_sim_kernel,
                         cudaFuncAttributeMaxDynamicSharedMemorySize, smem);

    dim3 grid((B + ROWS - 1) / ROWS);
    forward_sim_kernel<<<grid, THREADS, smem>>>(
        proj, enc, idm, mc, env_mean, env_var,
        W1, b1, W2, b2, W3, b3, out, B);
}

// round 2
// speedup vs baseline: 1.7674x; 1.7674x over previous
#include <cuda_runtime.h>
#include <cstdint>

#define T_STEPS 50
#define FEAT    14
#define MDIM    3
#define DT_     0.1f
#define ALPHA_  0.3f
#define DUMMY_DX_ 50.0f
#define ROWS    32          // rows per CTA
#define THREADS 128         // 4 warps, each warp owns 8 rows end-to-end

// ---------------- packed f32x2 helpers (sm_103a) ----------------
__device__ __forceinline__ void ffma2(unsigned long long &acc,
                                      unsigned long long a,
                                      unsigned long long b) {
    asm("fma.rn.f32x2 %0, %1, %2, %0;" : "+l"(acc) : "l"(a), "l"(b));
}
__device__ __forceinline__ float2 upk(unsigned long long v) {
    float2 f;
    asm("mov.b64 {%0, %1}, %2;" : "=f"(f.x), "=f"(f.y) : "l"(v));
    return f;
}

struct __align__(16) SmemLayout {
    float W2T[128][132];              // W2T[j][k] = W2[k][j]; pad 132 -> 4-phase LDS.128
    union {
        float inbuf[ROWS][256];       // phase-1 staging of [proj, enc]
        struct {
            float base_s[ROWS][128];  // base = [proj,enc]@W1[:256]+b1 (persists)
            float h1s[ROWS][128];     // per-step h1
        } bh;
    } u;
    float envmc[ROWS][12];            // normalized env(8) + mc(3), padded
    float w1v[11][128];               // W1 rows 256..266
};

__global__ void __launch_bounds__(THREADS, 2)
forward_sim_kernel(const float* __restrict__ proj,
                   const float* __restrict__ enc,
                   const float* __restrict__ idm,
                   const float* __restrict__ mc,
                   const float* __restrict__ env_mean,
                   const float* __restrict__ env_var,
                   const float* __restrict__ W1,
                   const float* __restrict__ b1,
                   const float* __restrict__ W2,
                   const float* __restrict__ b2,
                   const float* __restrict__ W3,
                   const float* __restrict__ b3,
                   float* __restrict__ out,
                   int B) {
    extern __shared__ char smem_raw[];
    SmemLayout* s = reinterpret_cast<SmemLayout*>(smem_raw);

    const int tid = threadIdx.x;
    const int l   = tid & 31;         // lane: owns cols {l, l+32, l+64, l+96}
    const int wq  = tid >> 5;         // warp: owns rows wq*8 .. wq*8+7
    const int row0 = blockIdx.x * ROWS;

    float* out_disp = out;                              // (B, 51)
    float* out_act  = out + (size_t)B * (T_STEPS + 1);  // (B, 50)

    // ---------------- stage constants ----------------
    for (int i = tid; i < 11 * 128; i += THREADS) {
        int rr = i >> 7, cc = i & 127;
        s->w1v[rr][cc] = W1[(256 + rr) * 128 + cc];
    }
    for (int i = tid; i < 128 * 128; i += THREADS) {
        int k = i >> 7, c = i & 127;          // coalesced read of W2[k][c]
        s->W2T[c][k] = W2[i];
    }
    for (int i = tid; i < ROWS * 128; i += THREADS) {
        int r = i >> 7, c = i & 127;
        int row = row0 + r;
        bool ok = row < B;
        s->u.inbuf[r][c]       = ok ? proj[(size_t)row * 128 + c] : 0.0f;
        s->u.inbuf[r][128 + c] = ok ? enc [(size_t)row * 128 + c] : 0.0f;
    }
    __syncthreads();

    // ---------------- phase 1: base = [proj,enc] @ W1[:256] + b1 (thread = col j) ----------------
    {
        const int j = tid;
        float bb[ROWS];
        const float b1j = b1[j];
#pragma unroll
        for (int r = 0; r < ROWS; r++) bb[r] = b1j;
        for (int k = 0; k < 256; k += 4) {
            float w0 = W1[(k + 0) * 128 + j];
            float w1 = W1[(k + 1) * 128 + j];
            float w2 = W1[(k + 2) * 128 + j];
            float w3 = W1[(k + 3) * 128 + j];
#pragma unroll
            for (int r = 0; r < ROWS; r++) {
                float4 x = *(const float4*)&s->u.inbuf[r][k];
                float v = bb[r];
                v = fmaf(x.x, w0, v);
                v = fmaf(x.y, w1, v);
                v = fmaf(x.z, w2, v);
                v = fmaf(x.w, w3, v);
                bb[r] = v;
            }
        }
        __syncthreads();   // all inbuf reads done before overwriting (base_s aliases inbuf)
#pragma unroll
        for (int r = 0; r < ROWS; r++) s->u.bh.base_s[r][j] = bb[r];
    }
    __syncthreads();

    // ---------------- per-thread loop-invariant registers ----------------
    float base[8][4];
#pragma unroll
    for (int r = 0; r < 8; r++)
#pragma unroll
        for (int c = 0; c < 4; c++)
            base[r][c] = s->u.bh.base_s[wq * 8 + r][l + 32 * c];

    float w1vj[11][4];
#pragma unroll
    for (int i = 0; i < 11; i++)
#pragma unroll
        for (int c = 0; c < 4; c++)
            w1vj[i][c] = s->w1v[i][l + 32 * c];

    float b2j[4], w3j[4];
#pragma unroll
    for (int c = 0; c < 4; c++) {
        b2j[c] = b2[l + 32 * c];
        w3j[c] = W3[l + 32 * c];
    }
    const float b3v = b3[0];

    // env normalization constants (used by lanes 0..7 only, cheap to load everywhere)
    float ems[8], eis[8];
#pragma unroll
    for (int i = 0; i < 8; i++) {
        ems[i] = env_mean[i];
        eis[i] = rsqrtf(env_var[i]);
    }

    // ---------------- per-row state (lanes 0..7 of each warp) ----------------
    const int myrow = row0 + wq * 8 + l;
    const bool lane8 = (l < 8) && (myrow < B);
    float ego_v = 0.f, ego_a = 0.f, ego_x = 0.f, disp = 0.f;
    float p_fv = 0.f, p_mv = 0.f, p_fx = 0.f, p_mx = 0.f, p_fa = 0.f, p_me = 0.f;
    float p_m0 = 0.f, p_m1 = 0.f, p_m2 = 0.f;
    if (lane8) {
        const float* p0 = idm + (size_t)myrow * T_STEPS * FEAT;
        ego_v = p0[0];
        ego_a = p0[11];
        ego_x = p0[3];
        out_disp[(size_t)myrow * (T_STEPS + 1)] = 0.0f;
        // prefetch t = 0
        p_fv = p0[1]; p_mv = p0[2]; p_fx = p0[4]; p_mx = p0[5];
        p_fa = p0[12]; p_me = p0[13];
        const float* mp = mc + (size_t)myrow * T_STEPS * MDIM;
        p_m0 = mp[0]; p_m1 = mp[1]; p_m2 = mp[2];
    }
    __syncthreads();

    const unsigned FULL = 0xffffffffu;
    float (*h1row)[128] = &s->u.bh.h1s[wq * 8];
    float (*envrow)[12] = &s->envmc[wq * 8];

    // ---------------- main time loop (warp-private) ----------------
    for (int t = 0; t < T_STEPS; t++) {
        // ---- phase A: env features (lanes 0..7) ----
        if (lane8) {
            float ef_dx = p_fx - ego_x;
            float em_dx = (p_mx - ego_x) * p_me + (1.0f - p_me) * DUMMY_DX_;
            float ef_dv = ego_v - p_fv;
            float em_dv = (ego_v - p_mv) * p_me;      // DUMMY_DV = 0
            float* e = envrow[l];
            e[0]  = (ego_v - ems[0]) * eis[0];
            e[1]  = (p_fv  - ems[1]) * eis[1];
            e[2]  = (ego_a - ems[2]) * eis[2];
            e[3]  = (p_fa  - ems[3]) * eis[3];
            e[4]  = (ef_dv - ems[4]) * eis[4];
            e[5]  = (ef_dx - ems[5]) * eis[5];
            e[6]  = (em_dv - ems[6]) * eis[6];
            e[7]  = (em_dx - ems[7]) * eis[7];
            e[8]  = p_m0;
            e[9]  = p_m1;
            e[10] = p_m2;
        }
        __syncwarp(FULL);

        // ---- prefetch t+1 inputs (state-independent) ----
        if (lane8) {
            int tn = (t + 1 < T_STEPS) ? t + 1 : T_STEPS - 1;
            const float* ip = idm + ((size_t)myrow * T_STEPS + tn) * FEAT;
            p_fv = ip[1]; p_mv = ip[2]; p_fx = ip[4]; p_mx = ip[5];
            p_fa = ip[12]; p_me = ip[13];
            const float* mp = mc + ((size_t)myrow * T_STEPS + tn) * MDIM;
            p_m0 = mp[0]; p_m1 = mp[1]; p_m2 = mp[2];
        }

        // ---- phase B: h1 = leaky(base + envmc @ W1v) ----
        float hb[8][4];
#pragma unroll
        for (int r = 0; r < 8; r++)
#pragma unroll
            for (int c = 0; c < 4; c++) hb[r][c] = base[r][c];
#pragma unroll
        for (int i = 0; i < 11; i++) {
#pragma unroll
            for (int r = 0; r < 8; r++) {
                float e = envrow[r][i];                // broadcast
                hb[r][0] = fmaf(e, w1vj[i][0], hb[r][0]);
                hb[r][1] = fmaf(e, w1vj[i][1], hb[r][1]);
                hb[r][2] = fmaf(e, w1vj[i][2], hb[r][2]);
                hb[r][3] = fmaf(e, w1vj[i][3], hb[r][3]);
            }
        }
#pragma unroll
        for (int r = 0; r < 8; r++)
#pragma unroll
            for (int c = 0; c < 4; c++) {
                float v = hb[r][c];
                v = fmaxf(v, ALPHA_ * v);              // leaky (alpha < 1)
                h1row[r][l + 32 * c] = v;
            }
        __syncwarp(FULL);

        // ---- phase C: h2pre[r][j] = sum_k h1[r][k] * W2[k][j] (f32x2, zero packing movs) ----
        unsigned long long acc[8][4];
#pragma unroll
        for (int r = 0; r < 8; r++)
#pragma unroll
            for (int c = 0; c < 4; c++) acc[r][c] = 0ull;

#pragma unroll 4
        for (int k4 = 0; k4 < 32; k4++) {
            ulonglong2 wv[4];
#pragma unroll
            for (int c = 0; c < 4; c++)
                wv[c] = *(const ulonglong2*)&s->W2T[l + 32 * c][k4 * 4];
            ulonglong2 hv[8];
#pragma unroll
            for (int r = 0; r < 8; r++)
                hv[r] = *(const ulonglong2*)&h1row[r][k4 * 4];
#pragma unroll
            for (int r = 0; r < 8; r++) {
                ffma2(acc[r][0], wv[0].x, hv[r].x);
                ffma2(acc[r][0], wv[0].y, hv[r].y);
                ffma2(acc[r][1], wv[1].x, hv[r].x);
                ffma2(acc[r][1], wv[1].y, hv[r].y);
                ffma2(acc[r][2], wv[2].x, hv[r].x);
                ffma2(acc[r][2], wv[2].y, hv[r].y);
                ffma2(acc[r][3], wv[3].x, hv[r].x);
                ffma2(acc[r][3], wv[3].y, hv[r].y);
            }
        }

        // ---- phase D: h2 = leaky(.), weight by W3 ----
        float g[8];
#pragma unroll
        for (int r = 0; r < 8; r++) {
            float gr = 0.0f;
#pragma unroll
            for (int c = 0; c < 4; c++) {
                float2 p = upk(acc[r][c]);
                float v = p.x + p.y + b2j[c];
                v = fmaxf(v, ALPHA_ * v);
                gr = fmaf(v, w3j[c], gr);
            }
            g[r] = gr;
        }

        // ---- phase E: warp butterfly reduction over 128 cols ----
#pragma unroll
        for (int off = 16; off > 0; off >>= 1) {
#pragma unroll
            for (int r = 0; r < 8; r++)
                g[r] += __shfl_xor_sync(FULL, g[r], off);
        }

        // ---- phase F: state update + outputs (lanes 0..7) ----
        if (lane8) {
            float s0 = (l & 1) ? g[1] : g[0];
            float s1 = (l & 1) ? g[3] : g[2];
            float s2 = (l & 1) ? g[5] : g[4];
            float s3 = (l & 1) ? g[7] : g[6];
            float t0 = (l & 2) ? s1 : s0;
            float t1 = (l & 2) ? s3 : s2;
            float a  = ((l & 4) ? t1 : t0) + b3v;
            float move = ego_v * DT_ + 0.5f * a * DT_ * DT_;
            disp  += move;
            ego_x += move;
            ego_v += a * DT_;
            ego_a  = a;
            out_act [(size_t)myrow * T_STEPS + t]           = a;
            out_disp[(size_t)myrow * (T_STEPS + 1) + t + 1] = disp;
        }
        __syncwarp(FULL);   // h1s/envmc overwrite fence for next iteration
    }
}

extern "C" void kernel_launch(void* const* d_in, const int* in_sizes, int n_in,
                              void* d_out, int out_size) {
    const float* proj     = (const float*)d_in[0];
    const float* enc      = (const float*)d_in[1];
    const float* idm      = (const float*)d_in[2];
    const float* mc       = (const float*)d_in[3];
    const float* env_mean = (const float*)d_in[4];
    const float* env_var  = (const float*)d_in[5];
    const float* W1       = (const float*)d_in[6];
    const float* b1       = (const float*)d_in[7];
    const float* W2       = (const float*)d_in[8];
    const float* b2       = (const float*)d_in[9];
    const float* W3       = (const float*)d_in[10];
    const float* b3       = (const float*)d_in[11];
    float* out = (float*)d_out;

    int B = in_sizes[0] / 128;   // proj_latent is (B, 128)

    int smem = (int)sizeof(SmemLayout);
    cudaFuncSetAttribute(forward_sim_kernel,
                         cudaFuncAttributeMaxDynamicSharedMemorySize, smem);

    dim3 grid((B + ROWS - 1) / ROWS);
    forward_sim_kernel<<<grid, THREADS, smem>>>(
        proj, enc, idm, mc, env_mean, env_var,
        W1, b1, W2, b2, W3, b3, out, B);
}

// round 4
// speedup vs baseline: 2.8944x; 1.6377x over previous
#include <cuda_runtime.h>
#include <cuda_bf16.h>
#include <cstdint>

#define T_STEPS 50
#define FEAT    14
#define MDIM    3
#define DT_     0.1f
#define ALPHA_  0.3f
#define DUMMY_DX_ 50.0f
#define ROWS    256
#define THREADS 256

// ---------------- f32x2 helpers ----------------
__device__ __forceinline__ void ffma2(unsigned long long &acc,
                                      unsigned long long a, unsigned long long b) {
    asm("fma.rn.f32x2 %0, %1, %2, %0;" : "+l"(acc) : "l"(a), "l"(b));
}
__device__ __forceinline__ unsigned long long pk(float lo, float hi) {
    unsigned long long r;
    asm("mov.b64 %0, {%1, %2};" : "=l"(r) : "f"(lo), "f"(hi));
    return r;
}
__device__ __forceinline__ float2 upk(unsigned long long v) {
    float2 f;
    asm("mov.b64 {%0, %1}, %2;" : "=f"(f.x), "=f"(f.y) : "l"(v));
    return f;
}
// packed bf16x2: hi-half = cvt(a), lo-half = cvt(b)
__device__ __forceinline__ unsigned cvt2(float hi, float lo) {
    unsigned r;
    asm("cvt.rn.bf16x2.f32 %0, %1, %2;" : "=r"(r) : "f"(hi), "f"(lo));
    return r;
}
__device__ __forceinline__ void mma16816(float &d0, float &d1, float &d2, float &d3,
                                         unsigned a0, unsigned a1, unsigned a2, unsigned a3,
                                         unsigned b0, unsigned b1) {
    asm("mma.sync.aligned.m16n8k16.row.col.f32.bf16.bf16.f32 "
        "{%0,%1,%2,%3}, {%4,%5,%6,%7}, {%8,%9}, {%0,%1,%2,%3};"
        : "+f"(d0), "+f"(d1), "+f"(d2), "+f"(d3)
        : "r"(a0), "r"(a1), "r"(a2), "r"(a3), "r"(b0), "r"(b1));
}

// ---------------- smem ----------------
struct __align__(16) Smem {
    float    baseFrag[8 * 2 * 16 * 32 * 4];   // 128KB  [((w*2+mt)*16+nt)*32+lam]*4+d
    unsigned bfragHi[8 * 8 * 32 * 4];         // 32KB   [((kt*8+q)*32+lam)*4+u]
    unsigned bfragLo[8 * 8 * 32 * 4];         // 32KB   (scratch aliases Hi+Lo during init)
    float    envS[ROWS][12];
    float    w1vS[11][128];
    float4   b2w3F[16 * 4];                   // [nt*4+g] = (b2[c],b2[c+1],W3[c],W3[c+1])
};

__global__ void __launch_bounds__(THREADS, 1)
forward_sim_kernel(const float* __restrict__ proj,
                   const float* __restrict__ enc,
                   const float* __restrict__ idm,
                   const float* __restrict__ mc,
                   const float* __restrict__ env_mean,
                   const float* __restrict__ env_var,
                   const float* __restrict__ W1,
                   const float* __restrict__ b1,
                   const float* __restrict__ W2,
                   const float* __restrict__ b2,
                   const float* __restrict__ W3,
                   const float* __restrict__ b3,
                   float* __restrict__ out,
                   int B) {
    extern __shared__ char smem_raw[];
    Smem* s = reinterpret_cast<Smem*>(smem_raw);

    const int tid = threadIdx.x;
    const int lam = tid & 31;          // lane
    const int w   = tid >> 5;          // warp (owns rows w*32 .. w*32+31)
    const int row0 = blockIdx.x * ROWS;

    float* out_disp = out;
    float* out_act  = out + (size_t)B * (T_STEPS + 1);

    // ================= INIT =================
    // small constants
    for (int i = tid; i < 11 * 128; i += THREADS) {
        int rr = i >> 7, cc = i & 127;
        s->w1vS[rr][cc] = W1[(256 + rr) * 128 + cc];
    }
    for (int i = tid; i < 64; i += THREADS) {
        int nt = i >> 2, g = i & 3;
        int c0 = nt * 8 + 2 * g;
        s->b2w3F[i] = make_float4(b2[c0], b2[c0 + 1], W3[c0], W3[c0 + 1]);
    }
    float ems[8], eis[8];
#pragma unroll
    for (int i = 0; i < 8; i++) { ems[i] = env_mean[i]; eis[i] = rsqrtf(env_var[i]); }
    const float b3v = b3[0];

    // --- base = [proj,enc] @ W1[:256] + b1, computed in 4 chunks of 64 rows,
    //     written into frag layout. Scratch = bfragHi..bfragLo area (64KB). ---
    {
        float* stageT = (float*)s->bfragHi;     // [256 k][64 r]
        const int j  = tid & 127;
        const int rh = tid >> 7;                // 0/1: rows rh*32..+31 of chunk
        const float b1j = b1[j];
        for (int c = 0; c < 4; c++) {
            __syncthreads();
            for (int idx = tid; idx < 64 * 256; idx += THREADS) {
                int r = idx & 63, k = idx >> 6;
                int grow = row0 + c * 64 + r;
                float v = 0.0f;
                if (grow < B) v = (k < 128) ? proj[(size_t)grow * 128 + k]
                                            : enc [(size_t)grow * 128 + (k - 128)];
                stageT[k * 64 + r] = v;
            }
            __syncthreads();
            unsigned long long acc[16];
            unsigned long long b1p = pk(b1j, b1j);
#pragma unroll
            for (int p = 0; p < 16; p++) acc[p] = b1p;
#pragma unroll 4
            for (int k = 0; k < 256; k++) {
                float wv = __ldg(&W1[k * 128 + j]);
                unsigned long long wk = pk(wv, wv);
                const unsigned long long* xp =
                    (const unsigned long long*)&stageT[k * 64 + rh * 32];
#pragma unroll
                for (int p = 0; p < 16; p++) ffma2(acc[p], xp[p], wk);
            }
            // scatter into frag layout
#pragma unroll
            for (int p = 0; p < 16; p++) {
                float2 v = upk(acc[p]);
#pragma unroll
                for (int h = 0; h < 2; h++) {
                    int rc = c * 64 + rh * 32 + 2 * p + h;    // row in CTA
                    float val = h ? v.y : v.x;
                    int ww  = rc >> 5;
                    int rr2 = rc & 31;
                    int mt  = rr2 >> 4;
                    int lf  = (rr2 & 7) * 4 + ((j & 7) >> 1);
                    int nt  = j >> 3;
                    int d   = ((rr2 >> 3) & 1) * 2 + (j & 1);
                    s->baseFrag[(((ww * 2 + mt) * 16 + nt) * 32 + lf) * 4 + d] = val;
                }
            }
        }
    }
    __syncthreads();

    // --- W2 -> bf16 hi/lo fragment tables ---
    for (int idx = tid; idx < 8 * 8 * 32 * 4; idx += THREADS) {
        int u  = idx & 3;
        int lf = (idx >> 2) & 31;
        int q  = (idx >> 7) & 7;
        int kt = idx >> 10;
        int nt  = 2 * q + (u >> 1);
        int reg = u & 1;
        int k0  = kt * 16 + reg * 8 + 2 * (lf & 3);
        int n   = nt * 8 + (lf >> 2);
        float w0 = W2[k0 * 128 + n];
        float w1 = W2[(k0 + 1) * 128 + n];
        float h0 = __bfloat162float(__float2bfloat16(w0));
        float h1 = __bfloat162float(__float2bfloat16(w1));
        s->bfragHi[idx] = cvt2(h1, h0);
        s->bfragLo[idx] = cvt2(w1 - h1, w0 - h0);
    }
    __syncthreads();

    // ================= per-thread state: each thread owns ONE row =================
    // own row (relative) = w*32 + lam/4 + 8*(lam%4); p[lam%4] after reduce = its a.
    const int rrel  = w * 32 + (lam >> 2) + 8 * (lam & 3);
    const int myrow = row0 + rrel;
    const bool rowok = myrow < B;

    float ego_v = 0.f, ego_a = 0.f, ego_x = 0.f, disp = 0.f;
    float p_fv = 0.f, p_mv = 0.f, p_fx = 0.f, p_mx = 0.f, p_fa = 0.f, p_me = 0.f;
    float p_m0 = 0.f, p_m1 = 0.f, p_m2 = 0.f;

    if (rowok) {
        const float* p0 = idm + (size_t)myrow * T_STEPS * FEAT;
        ego_v = p0[0]; ego_a = p0[11]; ego_x = p0[3];
        out_disp[(size_t)myrow * (T_STEPS + 1)] = 0.0f;
        p_fv = p0[1]; p_mv = p0[2]; p_fx = p0[4]; p_mx = p0[5];
        p_fa = p0[12]; p_me = p0[13];
        const float* mp = mc + (size_t)myrow * T_STEPS * MDIM;
        p_m0 = mp[0]; p_m1 = mp[1]; p_m2 = mp[2];
    }

    // write env for t=0
    {
        float* e = s->envS[rrel];
        if (rowok) {
            float ef_dx = p_fx - ego_x;
            float em_dx = (p_mx - ego_x) * p_me + (1.0f - p_me) * DUMMY_DX_;
            float ef_dv = ego_v - p_fv;
            float em_dv = (ego_v - p_mv) * p_me;
            e[0] = (ego_v - ems[0]) * eis[0];
            e[1] = (p_fv  - ems[1]) * eis[1];
            e[2] = (ego_a - ems[2]) * eis[2];
            e[3] = (p_fa  - ems[3]) * eis[3];
            e[4] = (ef_dv - ems[4]) * eis[4];
            e[5] = (ef_dx - ems[5]) * eis[5];
            e[6] = (em_dv - ems[6]) * eis[6];
            e[7] = (em_dx - ems[7]) * eis[7];
            e[8] = p_m0; e[9] = p_m1; e[10] = p_m2;
        } else {
#pragma unroll
            for (int i = 0; i < 11; i++) e[i] = 0.0f;
        }
        // prefetch t=1
        if (rowok) {
            const float* ip = idm + ((size_t)myrow * T_STEPS + 1) * FEAT;
            p_fv = ip[1]; p_mv = ip[2]; p_fx = ip[4]; p_mx = ip[5];
            p_fa = ip[12]; p_me = ip[13];
            const float* mp = mc + ((size_t)myrow * T_STEPS + 1) * MDIM;
            p_m0 = mp[0]; p_m1 = mp[1]; p_m2 = mp[2];
        }
    }
    __syncwarp();

    const int er0 = w * 32 + (lam >> 2);          // first env row of this thread's frags
    const float* baseW = &s->baseFrag[(w * 2) * 16 * 32 * 4];

    // ================= MAIN LOOP (warp-private; no block syncs) =================
    for (int t = 0; t < T_STEPS; t++) {
        // ---- phase B: h1pre = base + env @ W1v  (fp32, f32x2) ----
        unsigned long long d01[2][16], d23[2][16];
#pragma unroll
        for (int mt = 0; mt < 2; mt++)
#pragma unroll
            for (int nt = 0; nt < 16; nt++) {
                const float4* bp = (const float4*)&baseW[((mt * 16 + nt) * 32 + lam) * 4];
                float4 bv = *bp;
                d01[mt][nt] = pk(bv.x, bv.y);
                d23[mt][nt] = pk(bv.z, bv.w);
            }
#pragma unroll 1
        for (int i = 0; i < 11; i++) {
            unsigned long long ep[4];
#pragma unroll
            for (int u = 0; u < 4; u++) {
                float ev = s->envS[er0 + 8 * u][i];
                ep[u] = pk(ev, ev);
            }
            const int c00 = 2 * (lam & 3);
#pragma unroll
            for (int nt = 0; nt < 16; nt++) {
                unsigned long long wv =
                    *(const unsigned long long*)&s->w1vS[i][nt * 8 + c00];
                ffma2(d01[0][nt], wv, ep[0]);
                ffma2(d23[0][nt], wv, ep[1]);
                ffma2(d01[1][nt], wv, ep[2]);
                ffma2(d23[1][nt], wv, ep[3]);
            }
        }
        // leaky + bf16 hi/lo split (in regs; these are the phase-C A-fragments)
        unsigned ahi01[2][16], ahi23[2][16], alo01[2][16], alo23[2][16];
#pragma unroll
        for (int mt = 0; mt < 2; mt++)
#pragma unroll
            for (int nt = 0; nt < 16; nt++) {
                float2 v = upk(d01[mt][nt]);
                float v0 = fmaxf(v.x, ALPHA_ * v.x);
                float v1 = fmaxf(v.y, ALPHA_ * v.y);
                unsigned ph = cvt2(v1, v0);
                float f0 = __uint_as_float(ph << 16);
                float f1 = __uint_as_float(ph & 0xFFFF0000u);
                ahi01[mt][nt] = ph;
                alo01[mt][nt] = cvt2(v1 - f1, v0 - f0);
                float2 u2 = upk(d23[mt][nt]);
                float u0 = fmaxf(u2.x, ALPHA_ * u2.x);
                float u1 = fmaxf(u2.y, ALPHA_ * u2.y);
                unsigned qh = cvt2(u1, u0);
                float g0 = __uint_as_float(qh << 16);
                float g1 = __uint_as_float(qh & 0xFFFF0000u);
                ahi23[mt][nt] = qh;
                alo23[mt][nt] = cvt2(u1 - g1, u0 - g0);
            }

        // ---- phase C: h2 = h1 @ W2 via mma (3-pass bf16), N in 4 sweeps ----
        float p[4] = {0.f, 0.f, 0.f, 0.f};
#pragma unroll 1
        for (int ns = 0; ns < 4; ns++) {
            float D[2][4][4];
#pragma unroll
            for (int mt = 0; mt < 2; mt++)
#pragma unroll
                for (int nl = 0; nl < 4; nl++)
#pragma unroll
                    for (int d = 0; d < 4; d++) D[mt][nl][d] = 0.0f;

#pragma unroll
            for (int kt = 0; kt < 8; kt++) {
                const uint4 bh0 = *(const uint4*)&s->bfragHi[((kt * 8 + 2 * ns) * 32 + lam) * 4];
                const uint4 bh1 = *(const uint4*)&s->bfragHi[((kt * 8 + 2 * ns + 1) * 32 + lam) * 4];
                const uint4 bl0 = *(const uint4*)&s->bfragLo[((kt * 8 + 2 * ns) * 32 + lam) * 4];
                const uint4 bl1 = *(const uint4*)&s->bfragLo[((kt * 8 + 2 * ns + 1) * 32 + lam) * 4];
#pragma unroll
                for (int mt = 0; mt < 2; mt++) {
                    unsigned a0 = ahi01[mt][2 * kt],     a1 = ahi23[mt][2 * kt];
                    unsigned a2 = ahi01[mt][2 * kt + 1], a3 = ahi23[mt][2 * kt + 1];
                    unsigned l0 = alo01[mt][2 * kt],     l1 = alo23[mt][2 * kt];
                    unsigned l2 = alo01[mt][2 * kt + 1], l3 = alo23[mt][2 * kt + 1];
                    // Ahi * Bhi
                    mma16816(D[mt][0][0], D[mt][0][1], D[mt][0][2], D[mt][0][3],
                             a0, a1, a2, a3, bh0.x, bh0.y);
                    mma16816(D[mt][1][0], D[mt][1][1], D[mt][1][2], D[mt][1][3],
                             a0, a1, a2, a3, bh0.z, bh0.w);
                    mma16816(D[mt][2][0], D[mt][2][1], D[mt][2][2], D[mt][2][3],
                             a0, a1, a2, a3, bh1.x, bh1.y);
                    mma16816(D[mt][3][0], D[mt][3][1], D[mt][3][2], D[mt][3][3],
                             a0, a1, a2, a3, bh1.z, bh1.w);
                    // Alo * Bhi
                    mma16816(D[mt][0][0], D[mt][0][1], D[mt][0][2], D[mt][0][3],
                             l0, l1, l2, l3, bh0.x, bh0.y);
                    mma16816(D[mt][1][0], D[mt][1][1], D[mt][1][2], D[mt][1][3],
                             l0, l1, l2, l3, bh0.z, bh0.w);
                    mma16816(D[mt][2][0], D[mt][2][1], D[mt][2][2], D[mt][2][3],
                             l0, l1, l2, l3, bh1.x, bh1.y);
                    mma16816(D[mt][3][0], D[mt][3][1], D[mt][3][2], D[mt][3][3],
                             l0, l1, l2, l3, bh1.z, bh1.w);
                    // Ahi * Blo
                    mma16816(D[mt][0][0], D[mt][0][1], D[mt][0][2], D[mt][0][3],
                             a0, a1, a2, a3, bl0.x, bl0.y);
                    mma16816(D[mt][1][0], D[mt][1][1], D[mt][1][2], D[mt][1][3],
                             a0, a1, a2, a3, bl0.z, bl0.w);
                    mma16816(D[mt][2][0], D[mt][2][1], D[mt][2][2], D[mt][2][3],
                             a0, a1, a2, a3, bl1.x, bl1.y);
                    mma16816(D[mt][3][0], D[mt][3][1], D[mt][3][2], D[mt][3][3],
                             a0, a1, a2, a3, bl1.z, bl1.w);
                }
            }
            // sweep epilogue: leaky(h2 + b2) * W3, accumulate row partials
#pragma unroll
            for (int nl = 0; nl < 4; nl++) {
                int nt = 4 * ns + nl;
                float4 bw = s->b2w3F[nt * 4 + (lam & 3)];
#pragma unroll
                for (int mt = 0; mt < 2; mt++) {
                    float v0 = D[mt][nl][0] + bw.x;
                    float v1 = D[mt][nl][1] + bw.y;
                    float v2 = D[mt][nl][2] + bw.x;
                    float v3 = D[mt][nl][3] + bw.y;
                    v0 = fmaxf(v0, ALPHA_ * v0);
                    v1 = fmaxf(v1, ALPHA_ * v1);
                    v2 = fmaxf(v2, ALPHA_ * v2);
                    v3 = fmaxf(v3, ALPHA_ * v3);
                    p[2 * mt + 0] = fmaf(v0, bw.z, fmaf(v1, bw.w, p[2 * mt + 0]));
                    p[2 * mt + 1] = fmaf(v2, bw.z, fmaf(v3, bw.w, p[2 * mt + 1]));
                }
            }
        }

        // ---- reduce over the 4-lane column group ----
#pragma unroll
        for (int off = 1; off <= 2; off <<= 1) {
#pragma unroll
            for (int i = 0; i < 4; i++)
                p[i] += __shfl_xor_sync(0xffffffffu, p[i], off);
        }

        // ---- state update + outputs (thread's own row) ----
        {
            float a = p[lam & 3] + b3v;
            float move = ego_v * DT_ + 0.5f * a * DT_ * DT_;
            disp  += move;
            ego_x += move;
            ego_v += a * DT_;
            ego_a  = a;
            if (rowok) {
                out_act [(size_t)myrow * T_STEPS + t]           = a;
                out_disp[(size_t)myrow * (T_STEPS + 1) + t + 1] = disp;
            }
        }

        // ---- env for t+1 from prefetched inputs; prefetch t+2 ----
        if (t + 1 < T_STEPS) {
            float* e = s->envS[rrel];
            if (rowok) {
                float ef_dx = p_fx - ego_x;
                float em_dx = (p_mx - ego_x) * p_me + (1.0f - p_me) * DUMMY_DX_;
                float ef_dv = ego_v - p_fv;
                float em_dv = (ego_v - p_mv) * p_me;
                e[0] = (ego_v - ems[0]) * eis[0];
                e[1] = (p_fv  - ems[1]) * eis[1];
                e[2] = (ego_a - ems[2]) * eis[2];
                e[3] = (p_fa  - ems[3]) * eis[3];
                e[4] = (ef_dv - ems[4]) * eis[4];
                e[5] = (ef_dx - ems[5]) * eis[5];
                e[6] = (em_dv - ems[6]) * eis[6];
                e[7] = (em_dx - ems[7]) * eis[7];
                e[8] = p_m0; e[9] = p_m1; e[10] = p_m2;

                int tn = (t + 2 < T_STEPS) ? t + 2 : T_STEPS - 1;
                const float* ip = idm + ((size_t)myrow * T_STEPS + tn) * FEAT;
                p_fv = ip[1]; p_mv = ip[2]; p_fx = ip[4]; p_mx = ip[5];
                p_fa = ip[12]; p_me = ip[13];
                const float* mp = mc + ((size_t)myrow * T_STEPS + tn) * MDIM;
                p_m0 = mp[0]; p_m1 = mp[1]; p_m2 = mp[2];
            }
        }
        __syncwarp();
    }
}

extern "C" void kernel_launch(void* const* d_in, const int* in_sizes, int n_in,
                              void* d_out, int out_size) {
    const float* proj     = (const float*)d_in[0];
    const float* enc      = (const float*)d_in[1];
    const float* idm      = (const float*)d_in[2];
    const float* mc       = (const float*)d_in[3];
    const float* env_mean = (const float*)d_in[4];
    const float* env_var  = (const float*)d_in[5];
    const float* W1       = (const float*)d_in[6];
    const float* b1       = (const float*)d_in[7];
    const float* W2       = (const float*)d_in[8];
    const float* b2       = (const float*)d_in[9];
    const float* W3       = (const float*)d_in[10];
    const float* b3       = (const float*)d_in[11];
    float* out = (float*)d_out;

    int B = in_sizes[0] / 128;

    int smem = (int)sizeof(Smem);
    cudaFuncSetAttribute(forward_sim_kernel,
                         cudaFuncAttributeMaxDynamicSharedMemorySize, smem);

    dim3 grid((B + ROWS - 1) / ROWS);
    forward_sim_kernel<<<grid, THREADS, smem>>>(
        proj, enc, idm, mc, env_mean, env_var,
        W1, b1, W2, b2, W3, b3, out, B);
}

// round 5
// speedup vs baseline: 4.0918x; 1.4137x over previous
#include <cuda_runtime.h>
#include <cuda_bf16.h>
#include <cstdint>

#define T_STEPS 50
#define FEAT    14
#define MDIM    3
#define DT_     0.1f
#define ALPHA_  0.3f
#define DUMMY_DX_ 50.0f
#define ROWS    256
#define THREADS 512
#define NWARP   16

// ---------------- helpers ----------------
__device__ __forceinline__ void ffma2(unsigned long long &acc,
                                      unsigned long long a, unsigned long long b) {
    asm("fma.rn.f32x2 %0, %1, %2, %0;" : "+l"(acc) : "l"(a), "l"(b));
}
__device__ __forceinline__ unsigned long long pk(float lo, float hi) {
    unsigned long long r;
    asm("mov.b64 %0, {%1, %2};" : "=l"(r) : "f"(lo), "f"(hi));
    return r;
}
__device__ __forceinline__ float2 upk(unsigned long long v) {
    float2 f;
    asm("mov.b64 {%0, %1}, %2;" : "=f"(f.x), "=f"(f.y) : "l"(v));
    return f;
}
// packed bf16x2: high half = cvt(a), low half = cvt(b)
__device__ __forceinline__ unsigned cvt2(float hi, float lo) {
    unsigned r;
    asm("cvt.rn.bf16x2.f32 %0, %1, %2;" : "=r"(r) : "f"(hi), "f"(lo));
    return r;
}
__device__ __forceinline__ float lo_f(unsigned u) { return __uint_as_float(u << 16); }
__device__ __forceinline__ float hi_f(unsigned u) { return __uint_as_float(u & 0xFFFF0000u); }

__device__ __forceinline__ void mma16816(float &d0, float &d1, float &d2, float &d3,
                                         unsigned a0, unsigned a1, unsigned a2, unsigned a3,
                                         unsigned b0, unsigned b1) {
    asm("mma.sync.aligned.m16n8k16.row.col.f32.bf16.bf16.f32 "
        "{%0,%1,%2,%3}, {%4,%5,%6,%7}, {%8,%9}, {%0,%1,%2,%3};"
        : "+f"(d0), "+f"(d1), "+f"(d2), "+f"(d3)
        : "r"(a0), "r"(a1), "r"(a2), "r"(a3), "r"(b0), "r"(b1));
}

// ---------------- smem ----------------
struct __align__(16) Smem {
    float    baseFrag[NWARP * 16 * 32 * 4];   // 128KB  [(w*16+nt)*32+lam]*4+d
    unsigned bfragHi[8 * 8 * 32 * 4];         // 32KB   [((kt*8+q)*32+lam)*4+u]
    unsigned bfragLo[8 * 8 * 32 * 4];         // 32KB   (Hi+Lo also = 64KB init scratch)
    unsigned w1vHi[8 * 32 * 4];               // 4KB    phase-B W1v B-frags (1 kt)
    unsigned w1vLo[8 * 32 * 4];               // 4KB
    float    envS[ROWS][16];                  // 16KB   env padded to k16 (cols 11..15 = 0)
    float4   b2w3F[64];                       // 1KB    [nt*4+g] = (b2,b2',W3,W3')
    float    emsS[8];
    float    eisS[8];
};

__global__ void __launch_bounds__(THREADS)
forward_sim_kernel(const float* __restrict__ proj,
                   const float* __restrict__ enc,
                   const float* __restrict__ idm,
                   const float* __restrict__ mc,
                   const float* __restrict__ env_mean,
                   const float* __restrict__ env_var,
                   const float* __restrict__ W1,
                   const float* __restrict__ b1,
                   const float* __restrict__ W2,
                   const float* __restrict__ b2,
                   const float* __restrict__ W3,
                   const float* __restrict__ b3,
                   float* __restrict__ out,
                   int B) {
    extern __shared__ char smem_raw[];
    Smem* s = reinterpret_cast<Smem*>(smem_raw);

    const int tid = threadIdx.x;
    const int lam = tid & 31;
    const int w   = tid >> 5;              // warp owns rows w*16 .. w*16+15
    const int row0 = blockIdx.x * ROWS;

    float* out_disp = out;
    float* out_act  = out + (size_t)B * (T_STEPS + 1);

    // ================= INIT =================
    for (int i = tid; i < 64; i += THREADS) {
        int nt = i >> 2, g = i & 3;
        int c0 = nt * 8 + 2 * g;
        s->b2w3F[i] = make_float4(b2[c0], b2[c0 + 1], W3[c0], W3[c0 + 1]);
    }
    if (tid < 8) { s->emsS[tid] = env_mean[tid]; s->eisS[tid] = rsqrtf(env_var[tid]); }
    // zero env (incl. k-pad)
    for (int i = tid; i < ROWS * 16; i += THREADS) ((float*)s->envS)[i] = 0.0f;

    // W1v (rows 256..266 of W1) -> bf16 hi/lo B-frags, single k16 tile (pad k>=11 with 0)
    for (int idx = tid; idx < 8 * 32 * 4; idx += THREADS) {
        int u  = idx & 3;
        int lf = (idx >> 2) & 31;
        int q  = idx >> 7;
        int nt  = 2 * q + (u >> 1);
        int reg = u & 1;
        int k0  = reg * 8 + 2 * (lf & 3);
        int n   = nt * 8 + (lf >> 2);
        float w0 = (k0     < 11) ? W1[(256 + k0)     * 128 + n] : 0.0f;
        float w1 = (k0 + 1 < 11) ? W1[(256 + k0 + 1) * 128 + n] : 0.0f;
        float h0 = __bfloat162float(__float2bfloat16(w0));
        float h1 = __bfloat162float(__float2bfloat16(w1));
        s->w1vHi[idx] = cvt2(h1, h0);
        s->w1vLo[idx] = cvt2(w1 - h1, w0 - h0);
    }

    // --- base = [proj,enc] @ W1[:256] + b1 in 4 chunks of 64 rows; scratch = bfrag area ---
    {
        float* stageT = (float*)s->bfragHi;     // [256 k][64 r]
        const int j  = tid & 127;
        const int rh = tid >> 7;                // 0..3 -> rows rh*16..+15 of chunk
        const float b1j = b1[j];
        for (int c = 0; c < 4; c++) {
            __syncthreads();
            for (int idx = tid; idx < 64 * 64; idx += THREADS) {
                int r = idx & 63, kq = idx >> 6;
                int grow = row0 + c * 64 + r;
                float4 v = make_float4(0.f, 0.f, 0.f, 0.f);
                if (grow < B)
                    v = (kq < 32) ? *(const float4*)&proj[(size_t)grow * 128 + kq * 4]
                                  : *(const float4*)&enc [(size_t)grow * 128 + (kq - 32) * 4];
                stageT[(kq * 4 + 0) * 64 + r] = v.x;
                stageT[(kq * 4 + 1) * 64 + r] = v.y;
                stageT[(kq * 4 + 2) * 64 + r] = v.z;
                stageT[(kq * 4 + 3) * 64 + r] = v.w;
            }
            __syncthreads();
            unsigned long long acc[8];
            unsigned long long b1p = pk(b1j, b1j);
#pragma unroll
            for (int p = 0; p < 8; p++) acc[p] = b1p;
#pragma unroll 4
            for (int k = 0; k < 256; k++) {
                float wv = __ldg(&W1[k * 128 + j]);
                unsigned long long wk = pk(wv, wv);
                const unsigned long long* xp =
                    (const unsigned long long*)&stageT[k * 64 + rh * 16];
#pragma unroll
                for (int p = 0; p < 8; p++) ffma2(acc[p], xp[p], wk);
            }
#pragma unroll
            for (int p = 0; p < 8; p++) {
                float2 v = upk(acc[p]);
#pragma unroll
                for (int h = 0; h < 2; h++) {
                    int rc = c * 64 + rh * 16 + 2 * p + h;
                    float val = h ? v.y : v.x;
                    int ww  = rc >> 4;
                    int rr2 = rc & 15;
                    int lf  = (rr2 & 7) * 4 + ((j & 7) >> 1);
                    int nt  = j >> 3;
                    int d   = ((rr2 >> 3) & 1) * 2 + (j & 1);
                    s->baseFrag[((ww * 16 + nt) * 32 + lf) * 4 + d] = val;
                }
            }
        }
    }
    __syncthreads();

    // --- W2 -> bf16 hi/lo fragment tables (overwrites scratch) ---
    for (int idx = tid; idx < 8 * 8 * 32 * 4; idx += THREADS) {
        int u  = idx & 3;
        int lf = (idx >> 2) & 31;
        int q  = (idx >> 7) & 7;
        int kt = idx >> 10;
        int nt  = 2 * q + (u >> 1);
        int reg = u & 1;
        int k0  = kt * 16 + reg * 8 + 2 * (lf & 3);
        int n   = nt * 8 + (lf >> 2);
        float w0 = W2[k0 * 128 + n];
        float w1 = W2[(k0 + 1) * 128 + n];
        float h0 = __bfloat162float(__float2bfloat16(w0));
        float h1 = __bfloat162float(__float2bfloat16(w1));
        s->bfragHi[idx] = cvt2(h1, h0);
        s->bfragLo[idx] = cvt2(w1 - h1, w0 - h0);
    }
    __syncthreads();

    // ================= per-thread row ownership =================
    const int k0e = 2 * (lam & 3);          // A-frag k offset (cols / features)
    const int qr  = lam >> 2;               // frag row index
    const int er0 = w * 16 + qr;
    const bool own = (lam & 3) < 2;         // lanes owning a row
    const int rrel  = w * 16 + qr + 8 * (lam & 1);
    const int myrow = row0 + rrel;
    const bool rowok = own && (myrow < B);

    float ego_v = 0.f, ego_a = 0.f, ego_x = 0.f, disp = 0.f;
    float p_fv = 0.f, p_mv = 0.f, p_fx = 0.f, p_mx = 0.f, p_fa = 0.f, p_me = 0.f;
    float p_m0 = 0.f, p_m1 = 0.f, p_m2 = 0.f;

    if (rowok) {
        const float* p0 = idm + (size_t)myrow * T_STEPS * FEAT;
        ego_v = p0[0]; ego_a = p0[11]; ego_x = p0[3];
        out_disp[(size_t)myrow * (T_STEPS + 1)] = 0.0f;
        p_fv = p0[1]; p_mv = p0[2]; p_fx = p0[4]; p_mx = p0[5];
        p_fa = p0[12]; p_me = p0[13];
        const float* mp = mc + (size_t)myrow * T_STEPS * MDIM;
        p_m0 = mp[0]; p_m1 = mp[1]; p_m2 = mp[2];
    }
    // env for t=0 + prefetch t=1
    if (own) {
        float* e = s->envS[rrel];
        if (rowok) {
            float ef_dx = p_fx - ego_x;
            float em_dx = (p_mx - ego_x) * p_me + (1.0f - p_me) * DUMMY_DX_;
            float ef_dv = ego_v - p_fv;
            float em_dv = (ego_v - p_mv) * p_me;
            e[0] = (ego_v - s->emsS[0]) * s->eisS[0];
            e[1] = (p_fv  - s->emsS[1]) * s->eisS[1];
            e[2] = (ego_a - s->emsS[2]) * s->eisS[2];
            e[3] = (p_fa  - s->emsS[3]) * s->eisS[3];
            e[4] = (ef_dv - s->emsS[4]) * s->eisS[4];
            e[5] = (ef_dx - s->emsS[5]) * s->eisS[5];
            e[6] = (em_dv - s->emsS[6]) * s->eisS[6];
            e[7] = (em_dx - s->emsS[7]) * s->eisS[7];
            e[8] = p_m0; e[9] = p_m1; e[10] = p_m2;
            const float* ip = idm + ((size_t)myrow * T_STEPS + 1) * FEAT;
            p_fv = ip[1]; p_mv = ip[2]; p_fx = ip[4]; p_mx = ip[5];
            p_fa = ip[12]; p_me = ip[13];
            const float* mp = mc + ((size_t)myrow * T_STEPS + 1) * MDIM;
            p_m0 = mp[0]; p_m1 = mp[1]; p_m2 = mp[2];
        }
    }
    const float b3v = b3[0];
    __syncthreads();

    const float* baseW = &s->baseFrag[(w * 16) * 32 * 4];

    // ================= MAIN LOOP (warp-private) =================
    for (int t = 0; t < T_STEPS; t++) {
        // ---- phase B (MMA): h1pre frags = base + env @ W1v ----
        float D16[16][4];
#pragma unroll
        for (int nt = 0; nt < 16; nt++)
            *(float4*)D16[nt] = *(const float4*)&baseW[(nt * 32 + lam) * 4];

        float2 ea0 = *(const float2*)&s->envS[er0][k0e];
        float2 ea1 = *(const float2*)&s->envS[er0 + 8][k0e];
        float2 ea2 = *(const float2*)&s->envS[er0][k0e + 8];
        float2 ea3 = *(const float2*)&s->envS[er0 + 8][k0e + 8];
        unsigned eh0 = cvt2(ea0.y, ea0.x), eh1 = cvt2(ea1.y, ea1.x);
        unsigned eh2 = cvt2(ea2.y, ea2.x), eh3 = cvt2(ea3.y, ea3.x);
        unsigned el0 = cvt2(ea0.y - hi_f(eh0), ea0.x - lo_f(eh0));
        unsigned el1 = cvt2(ea1.y - hi_f(eh1), ea1.x - lo_f(eh1));
        unsigned el2 = cvt2(ea2.y - hi_f(eh2), ea2.x - lo_f(eh2));
        unsigned el3 = cvt2(ea3.y - hi_f(eh3), ea3.x - lo_f(eh3));

#pragma unroll
        for (int q = 0; q < 8; q++) {
            uint4 wh = *(const uint4*)&s->w1vHi[(q * 32 + lam) * 4];
            uint4 wl = *(const uint4*)&s->w1vLo[(q * 32 + lam) * 4];
            mma16816(D16[2*q][0], D16[2*q][1], D16[2*q][2], D16[2*q][3],
                     eh0, eh1, eh2, eh3, wh.x, wh.y);
            mma16816(D16[2*q+1][0], D16[2*q+1][1], D16[2*q+1][2], D16[2*q+1][3],
                     eh0, eh1, eh2, eh3, wh.z, wh.w);
            mma16816(D16[2*q][0], D16[2*q][1], D16[2*q][2], D16[2*q][3],
                     el0, el1, el2, el3, wh.x, wh.y);
            mma16816(D16[2*q+1][0], D16[2*q+1][1], D16[2*q+1][2], D16[2*q+1][3],
                     el0, el1, el2, el3, wh.z, wh.w);
            mma16816(D16[2*q][0], D16[2*q][1], D16[2*q][2], D16[2*q][3],
                     eh0, eh1, eh2, eh3, wl.x, wl.y);
            mma16816(D16[2*q+1][0], D16[2*q+1][1], D16[2*q+1][2], D16[2*q+1][3],
                     eh0, eh1, eh2, eh3, wl.z, wl.w);
        }

        // ---- leaky + bf16 hi/lo split -> phase-C A-frags ----
        unsigned ahi01[16], ahi23[16], alo01[16], alo23[16];
#pragma unroll
        for (int nt = 0; nt < 16; nt++) {
            float v0 = D16[nt][0], v1 = D16[nt][1], v2 = D16[nt][2], v3 = D16[nt][3];
            v0 = fmaxf(v0, ALPHA_ * v0);
            v1 = fmaxf(v1, ALPHA_ * v1);
            v2 = fmaxf(v2, ALPHA_ * v2);
            v3 = fmaxf(v3, ALPHA_ * v3);
            unsigned ph = cvt2(v1, v0);
            ahi01[nt] = ph;
            alo01[nt] = cvt2(v1 - hi_f(ph), v0 - lo_f(ph));
            unsigned qh = cvt2(v3, v2);
            ahi23[nt] = qh;
            alo23[nt] = cvt2(v3 - hi_f(qh), v2 - lo_f(qh));
        }

        // ---- phase C: h2 = h1 @ W2 (3-pass bf16), N in 4 sweeps ----
        float pr0 = 0.0f, pr1 = 0.0f;
#pragma unroll 1
        for (int ns = 0; ns < 4; ns++) {
            float D[4][4];
#pragma unroll
            for (int nl = 0; nl < 4; nl++)
#pragma unroll
                for (int d = 0; d < 4; d++) D[nl][d] = 0.0f;

#pragma unroll
            for (int kt = 0; kt < 8; kt++) {
                const uint4 bh0 = *(const uint4*)&s->bfragHi[((kt * 8 + 2 * ns) * 32 + lam) * 4];
                const uint4 bh1 = *(const uint4*)&s->bfragHi[((kt * 8 + 2 * ns + 1) * 32 + lam) * 4];
                const uint4 bl0 = *(const uint4*)&s->bfragLo[((kt * 8 + 2 * ns) * 32 + lam) * 4];
                const uint4 bl1 = *(const uint4*)&s->bfragLo[((kt * 8 + 2 * ns + 1) * 32 + lam) * 4];
                unsigned a0 = ahi01[2 * kt],     a1 = ahi23[2 * kt];
                unsigned a2 = ahi01[2 * kt + 1], a3 = ahi23[2 * kt + 1];
                unsigned l0 = alo01[2 * kt],     l1 = alo23[2 * kt];
                unsigned l2 = alo01[2 * kt + 1], l3 = alo23[2 * kt + 1];
                mma16816(D[0][0], D[0][1], D[0][2], D[0][3], a0, a1, a2, a3, bh0.x, bh0.y);
                mma16816(D[1][0], D[1][1], D[1][2], D[1][3], a0, a1, a2, a3, bh0.z, bh0.w);
                mma16816(D[2][0], D[2][1], D[2][2], D[2][3], a0, a1, a2, a3, bh1.x, bh1.y);
                mma16816(D[3][0], D[3][1], D[3][2], D[3][3], a0, a1, a2, a3, bh1.z, bh1.w);
                mma16816(D[0][0], D[0][1], D[0][2], D[0][3], l0, l1, l2, l3, bh0.x, bh0.y);
                mma16816(D[1][0], D[1][1], D[1][2], D[1][3], l0, l1, l2, l3, bh0.z, bh0.w);
                mma16816(D[2][0], D[2][1], D[2][2], D[2][3], l0, l1, l2, l3, bh1.x, bh1.y);
                mma16816(D[3][0], D[3][1], D[3][2], D[3][3], l0, l1, l2, l3, bh1.z, bh1.w);
                mma16816(D[0][0], D[0][1], D[0][2], D[0][3], a0, a1, a2, a3, bl0.x, bl0.y);
                mma16816(D[1][0], D[1][1], D[1][2], D[1][3], a0, a1, a2, a3, bl0.z, bl0.w);
                mma16816(D[2][0], D[2][1], D[2][2], D[2][3], a0, a1, a2, a3, bl1.x, bl1.y);
                mma16816(D[3][0], D[3][1], D[3][2], D[3][3], a0, a1, a2, a3, bl1.z, bl1.w);
            }
#pragma unroll
            for (int nl = 0; nl < 4; nl++) {
                int nt = 4 * ns + nl;
                float4 bw = s->b2w3F[nt * 4 + (lam & 3)];
                float v0 = D[nl][0] + bw.x;
                float v1 = D[nl][1] + bw.y;
                float v2 = D[nl][2] + bw.x;
                float v3 = D[nl][3] + bw.y;
                v0 = fmaxf(v0, ALPHA_ * v0);
                v1 = fmaxf(v1, ALPHA_ * v1);
                v2 = fmaxf(v2, ALPHA_ * v2);
                v3 = fmaxf(v3, ALPHA_ * v3);
                pr0 = fmaf(v0, bw.z, fmaf(v1, bw.w, pr0));
                pr1 = fmaf(v2, bw.z, fmaf(v3, bw.w, pr1));
            }
        }

        // ---- quad reduce over n-columns ----
        pr0 += __shfl_xor_sync(0xffffffffu, pr0, 1);
        pr0 += __shfl_xor_sync(0xffffffffu, pr0, 2);
        pr1 += __shfl_xor_sync(0xffffffffu, pr1, 1);
        pr1 += __shfl_xor_sync(0xffffffffu, pr1, 2);

        __syncwarp();   // all envS reads for step t done before rewrite

        // ---- state update + outputs + env(t+1) + prefetch(t+2) ----
        if (rowok) {
            float a = ((lam & 1) ? pr1 : pr0) + b3v;
            float move = ego_v * DT_ + 0.5f * a * DT_ * DT_;
            disp  += move;
            ego_x += move;
            ego_v += a * DT_;
            ego_a  = a;
            out_act [(size_t)myrow * T_STEPS + t]           = a;
            out_disp[(size_t)myrow * (T_STEPS + 1) + t + 1] = disp;

            if (t + 1 < T_STEPS) {
                float* e = s->envS[rrel];
                float ef_dx = p_fx - ego_x;
                float em_dx = (p_mx - ego_x) * p_me + (1.0f - p_me) * DUMMY_DX_;
                float ef_dv = ego_v - p_fv;
                float em_dv = (ego_v - p_mv) * p_me;
                e[0] = (ego_v - s->emsS[0]) * s->eisS[0];
                e[1] = (p_fv  - s->emsS[1]) * s->eisS[1];
                e[2] = (ego_a - s->emsS[2]) * s->eisS[2];
                e[3] = (p_fa  - s->emsS[3]) * s->eisS[3];
                e[4] = (ef_dv - s->emsS[4]) * s->eisS[4];
                e[5] = (ef_dx - s->emsS[5]) * s->eisS[5];
                e[6] = (em_dv - s->emsS[6]) * s->eisS[6];
                e[7] = (em_dx - s->emsS[7]) * s->eisS[7];
                e[8] = p_m0; e[9] = p_m1; e[10] = p_m2;

                int tn = (t + 2 < T_STEPS) ? t + 2 : T_STEPS - 1;
                const float* ip = idm + ((size_t)myrow * T_STEPS + tn) * FEAT;
                p_fv = ip[1]; p_mv = ip[2]; p_fx = ip[4]; p_mx = ip[5];
                p_fa = ip[12]; p_me = ip[13];
                const float* mp = mc + ((size_t)myrow * T_STEPS + tn) * MDIM;
                p_m0 = mp[0]; p_m1 = mp[1]; p_m2 = mp[2];
            }
        }
        __syncwarp();   // env writes visible before next iteration's reads
    }
}

extern "C" void kernel_launch(void* const* d_in, const int* in_sizes, int n_in,
                              void* d_out, int out_size) {
    const float* proj     = (const float*)d_in[0];
    const float* enc      = (const float*)d_in[1];
    const float* idm      = (const float*)d_in[2];
    const float* mc       = (const float*)d_in[3];
    const float* env_mean = (const float*)d_in[4];
    const float* env_var  = (const float*)d_in[5];
    const float* W1       = (const float*)d_in[6];
    const float* b1       = (const float*)d_in[7];
    const float* W2       = (const float*)d_in[8];
    const float* b2       = (const float*)d_in[9];
    const float* W3       = (const float*)d_in[10];
    const float* b3       = (const float*)d_in[11];
    float* out = (float*)d_out;

    int B = in_sizes[0] / 128;

    int smem = (int)sizeof(Smem);
    cudaFuncSetAttribute(forward_sim_kernel,
                         cudaFuncAttributeMaxDynamicSharedMemorySize, smem);

    dim3 grid((B + ROWS - 1) / ROWS);
    forward_sim_kernel<<<grid, THREADS, smem>>>(
        proj, enc, idm, mc, env_mean, env_var,
        W1, b1, W2, b2, W3, b3, out, B);
}